// round 11
// baseline (speedup 1.0000x reference)
#include <cuda_runtime.h>
#include <cuda_fp16.h>
#include <cstdint>
#include <float.h>

#define NROWS   65536
#define DIM     512
#define KCENT   256
#define BM      64           // rows per tile
#define KC      64           // fp16 k-chunk
#define NCHUNK  (DIM / KC)   // 8
#define NTILES  (NROWS / BM) // 1024
#define THREADS 256
#define NCTAS   296          // 2 per SM, persistent
#define TH      0.8f         // certainty margin (validated R6)
#define MAXC    16

// 144-byte padded rows: row r starts at bank 4r (mod 32) -> conflict-free
// 16B ldmatrix reads with NO swizzle; all addresses are base + immediates.
#define ROWB      144
#define A_TILE    (BM * ROWB)            // 9216
#define B_TILE    (KCENT * ROWB)         // 36864
#define OFF_A0    0
#define OFF_A1    A_TILE                 // 9216
#define OFF_B0    (2 * A_TILE)           // 18432
#define OFF_B1    (2 * A_TILE + B_TILE)  // 55296
#define SMEM_BYTES (2 * A_TILE + 2 * B_TILE) // 92160

// ---------------------------------------------------------------------------
// device globals (scratch; no allocs allowed)
// ---------------------------------------------------------------------------
__device__ float   g_cn2[KCENT];
__device__ __half  g_chf[KCENT * DIM];
__device__ int     g_tile_ctr;
__device__ int     g_amb_cnt;
__device__ int     g_amb_row[NROWS];
__device__ int     g_amb_n[NROWS];
__device__ int     g_amb_cand[NROWS][MAXC];

// ---------------------------------------------------------------------------
// helpers
// ---------------------------------------------------------------------------
__device__ __forceinline__ uint32_t smem_u32(const void* p) {
    uint32_t a;
    asm("{ .reg .u64 t; cvta.to.shared.u64 t, %1; cvt.u32.u64 %0, t; }"
        : "=r"(a) : "l"(p));
    return a;
}

#define LDM_X4(r, addr)                                                     \
    asm volatile("ldmatrix.sync.aligned.m8n8.x4.shared.b16 {%0,%1,%2,%3}, [%4];" \
        : "=r"((r)[0]), "=r"((r)[1]), "=r"((r)[2]), "=r"((r)[3]) : "r"(addr))
// fp16 inputs, fp16 ACCUMULATE (packed f16x2 D/C regs)
#define MMA_F16ACC(d, a, b0, b1)                                            \
    asm volatile("mma.sync.aligned.m16n8k16.row.col.f16.f16.f16.f16 "       \
        "{%0,%1}, {%2,%3,%4,%5}, {%6,%7}, {%0,%1};"                         \
        : "+r"((d)[0]), "+r"((d)[1])                                        \
        : "r"((a)[0]), "r"((a)[1]), "r"((a)[2]), "r"((a)[3]), "r"(b0), "r"(b1))
#define CP_ASYNC16(dst, src)                                                \
    asm volatile("cp.async.cg.shared.global [%0], [%1], 16;" :: "r"(dst), "l"(src))
#define CP_COMMIT() asm volatile("cp.async.commit_group;" ::: "memory")
#define CP_WAIT0()  asm volatile("cp.async.wait_group 0;" ::: "memory")
#define STS64(addr, v0, v1)                                                 \
    asm volatile("st.shared.v2.u32 [%0], {%1, %2};" :: "r"(addr), "r"(v0), "r"(v1))

__device__ __forceinline__ bool closer(float s, int i, float s2, int i2) {
    return (s < s2) || (s == s2 && i < i2);
}
__device__ __forceinline__ void ins4(float v, int i, float s[4], int ix[4]) {
    if (closer(v, i, s[3], ix[3])) {
        s[3] = v; ix[3] = i;
        #pragma unroll
        for (int q = 3; q > 0; q--) {
            if (closer(s[q], ix[q], s[q - 1], ix[q - 1])) {
                float tv = s[q];  s[q] = s[q - 1];  s[q - 1] = tv;
                int   ti = ix[q]; ix[q] = ix[q - 1]; ix[q - 1] = ti;
            }
        }
    }
}

// ---------------------------------------------------------------------------
// prep: exact centroid norms + fp16 centroid copy + zero counters
// ---------------------------------------------------------------------------
__global__ void prep_kernel(const float* __restrict__ cent) {
    __shared__ float ws[8];
    int b = blockIdx.x, t = threadIdx.x;
    if (b == 0 && t == 0) { g_amb_cnt = 0; g_tile_ctr = 0; }
    float v0 = cent[b * DIM + 2 * t];
    float v1 = cent[b * DIM + 2 * t + 1];
    g_chf[b * DIM + 2 * t]     = __float2half_rn(v0);
    g_chf[b * DIM + 2 * t + 1] = __float2half_rn(v1);
    float p = fmaf(v0, v0, v1 * v1);
    #pragma unroll
    for (int o = 16; o; o >>= 1) p += __shfl_xor_sync(0xFFFFFFFFu, p, o);
    if ((t & 31) == 0) ws[t >> 5] = p;
    __syncthreads();
    if (t == 0) {
        float s = 0.f;
        #pragma unroll
        for (int w = 0; w < 8; w++) s += ws[w];
        g_cn2[b] = s;
    }
}

// ---------------------------------------------------------------------------
// main: persistent CTAs (dynamic tile claim). 64-row tile x 256 centroids,
// fp16 mma.sync (f16 acc per chunk -> fp32), 144B-row unswizzled smem,
// x4-paired B ldmatrix, double-buffered, top-4 + certainty, gather.
// ---------------------------------------------------------------------------
__global__ __launch_bounds__(THREADS, 2)
void negsample_mma_kernel(const float* __restrict__ emb,
                          const float* __restrict__ cent,
                          float* __restrict__ out) {
    extern __shared__ __align__(128) char smem[];
    __shared__ float cns[KCENT];
    __shared__ int   sidx[BM];
    __shared__ int   snext;

    const uint32_t sb = smem_u32(smem);
    const int tid  = threadIdx.x;
    const int lane = tid & 31;
    const int wid  = tid >> 5;
    const int wr   = wid >> 2;        // 0..1 (row half)
    const int wc   = wid & 3;         // 0..3 (col quarter)

    cns[tid] = g_cn2[tid];

    const uint32_t offA[2] = {OFF_A0, OFF_A1};
    const uint32_t offB[2] = {OFF_B0, OFF_B1};

    // ---- additive lane bases (computed once; all later addrs = base+imm) ----
    const uint32_t aLdB = sb + (uint32_t)((wr * 32 + (lane & 15)) * ROWB)
                             + ((uint32_t)(lane >> 4) << 4);
    const uint32_t bLdB = sb + (uint32_t)((wc * 64 + (lane & 7) + ((lane >> 4) << 3)) * ROWB)
                             + (((uint32_t)(lane >> 3) & 1u) << 4);
    const uint32_t aStB = sb + (uint32_t)((tid >> 4) * ROWB) + (uint32_t)((tid & 15) * 8);
    const uint32_t bStB = sb + (uint32_t)((tid >> 3) * ROWB) + (uint32_t)((tid & 7) * 16);

    const int ar  = tid >> 4;         // A gmem row base
    const int ac4 = tid & 15;
    const int br  = tid >> 3;         // B gmem row base
    const int bg  = tid & 7;

    float* candv = (float*)(smem);          // aliases A0 (safe: barriers below)
    int*   candi = (int*)(smem + 4096);

    while (true) {
        if (tid == 0) snext = atomicAdd(&g_tile_ctr, 1);
        __syncthreads();
        const int tile = snext;
        if (tile >= NTILES) break;
        const int row0 = tile * BM;

        float acc[2][8][4];
        #pragma unroll
        for (int t = 0; t < 2; t++)
            #pragma unroll
            for (int j = 0; j < 8; j++)
                #pragma unroll
                for (int q = 0; q < 4; q++) acc[t][j][q] = 0.f;

        // ---- prologue: A regs chunk 0, cp.async B chunk 0 -> buf 0 ----
        float4 areg[4];
        {
            const float* ebase = emb + (size_t)row0 * DIM;
            #pragma unroll
            for (int i = 0; i < 4; i++)
                areg[i] = *(const float4*)(ebase + (size_t)(ar + i * 16) * DIM + ac4 * 4);
            #pragma unroll
            for (int i = 0; i < 8; i++)
                CP_ASYNC16(bStB + OFF_B0 + (uint32_t)(i * 32 * ROWB),
                           g_chf + (size_t)(br + i * 32) * DIM + bg * 8);
            CP_COMMIT();
        }

        for (int kc = 0; kc < NCHUNK; kc++) {
            const int cur = kc & 1;

            // ---- convert prefetched A regs -> fp16 smem (144B rows) ----
            #pragma unroll
            for (int i = 0; i < 4; i++) {
                __half2 h0 = __floats2half2_rn(areg[i].x, areg[i].y);
                __half2 h1 = __floats2half2_rn(areg[i].z, areg[i].w);
                STS64(aStB + offA[cur] + (uint32_t)(i * 16 * ROWB),
                      *(uint32_t*)&h0, *(uint32_t*)&h1);
            }
            CP_WAIT0();
            __syncthreads();

            // ---- prefetch next chunk (overlaps MMA) ----
            if (kc + 1 < NCHUNK) {
                const float* ebase = emb + (size_t)row0 * DIM + (kc + 1) * KC;
                #pragma unroll
                for (int i = 0; i < 4; i++)
                    areg[i] = *(const float4*)(ebase + (size_t)(ar + i * 16) * DIM + ac4 * 4);
                #pragma unroll
                for (int i = 0; i < 8; i++)
                    CP_ASYNC16(bStB + offB[1 - cur] + (uint32_t)(i * 32 * ROWB),
                               g_chf + (size_t)(br + i * 32) * DIM + (kc + 1) * KC + bg * 8);
                CP_COMMIT();
            }

            // ---- two t-halves; f16 acc within chunk, promote to fp32 ----
            const uint32_t aB = aLdB + offA[cur];
            const uint32_t bB = bLdB + offB[cur];
            #pragma unroll
            for (int t = 0; t < 2; t++) {
                uint32_t cf[8][2];
                #pragma unroll
                for (int j = 0; j < 8; j++) { cf[j][0] = 0u; cf[j][1] = 0u; }

                #pragma unroll
                for (int s = 0; s < 4; s++) {
                    uint32_t a[4];
                    LDM_X4(a, aB + (uint32_t)(t * 16 * ROWB + s * 32));
                    #pragma unroll
                    for (int j2 = 0; j2 < 4; j2++) {
                        uint32_t b4[4];
                        LDM_X4(b4, bB + (uint32_t)(j2 * 16 * ROWB + s * 32));
                        MMA_F16ACC(cf[2 * j2],     a, b4[0], b4[1]);
                        MMA_F16ACC(cf[2 * j2 + 1], a, b4[2], b4[3]);
                    }
                }
                #pragma unroll
                for (int j = 0; j < 8; j++) {
                    float2 f0 = __half22float2(*(__half2*)&cf[j][0]);
                    float2 f1 = __half22float2(*(__half2*)&cf[j][1]);
                    acc[t][j][0] += f0.x; acc[t][j][1] += f0.y;
                    acc[t][j][2] += f1.x; acc[t][j][3] += f1.y;
                }
            }
            // no trailing sync: next iter writes the opposite buffer only
        }
        __syncthreads();   // all MMA smem reads done -> reuse smem for candidates

        // ---- per-lane scores + top-4 per row; merge across 4 lanes ----
        #pragma unroll
        for (int t = 0; t < 2; t++) {
            #pragma unroll
            for (int h = 0; h < 2; h++) {
                int row = wr * 32 + t * 16 + h * 8 + (lane >> 2);
                float s4[4]; int i4[4];
                #pragma unroll
                for (int q = 0; q < 4; q++) { s4[q] = FLT_MAX; i4[q] = 0x7fffffff; }
                #pragma unroll
                for (int j = 0; j < 8; j++) {
                    #pragma unroll
                    for (int b = 0; b < 2; b++) {
                        int   col = wc * 64 + j * 8 + (lane & 3) * 2 + b;
                        float sc  = fmaf(-2.0f, acc[t][j][h * 2 + b], cns[col]);
                        ins4(sc, col, s4, i4);
                    }
                }
                // butterfly merge: snapshot partner entries BEFORE inserting
                #pragma unroll
                for (int off = 1; off <= 2; off <<= 1) {
                    float ov[4]; int oi[4];
                    #pragma unroll
                    for (int q = 0; q < 4; q++) {
                        ov[q] = __shfl_xor_sync(0xFFFFFFFFu, s4[q], off);
                        oi[q] = __shfl_xor_sync(0xFFFFFFFFu, i4[q], off);
                    }
                    #pragma unroll
                    for (int q = 0; q < 4; q++) ins4(ov[q], oi[q], s4, i4);
                }
                if ((lane & 3) == 0) {
                    int base = (row * 4 + wc) * 4;
                    #pragma unroll
                    for (int q = 0; q < 4; q++) { candv[base + q] = s4[q]; candi[base + q] = i4[q]; }
                }
            }
        }
        __syncthreads();

        // ---- final per-row merge of 16 candidates; certainty test ----
        if (tid < BM) {
            int row = tid;
            float s4[4]; int i4[4];
            #pragma unroll
            for (int q = 0; q < 4; q++) { s4[q] = FLT_MAX; i4[q] = 0x7fffffff; }
            #pragma unroll
            for (int w = 0; w < 4; w++)
                #pragma unroll
                for (int q = 0; q < 4; q++)
                    ins4(candv[(row * 4 + w) * 4 + q], candi[(row * 4 + w) * 4 + q], s4, i4);

            sidx[row] = i4[1];
            bool amb = (s4[1] - s4[0] <= TH) || (s4[2] - s4[1] <= TH);
            if (amb) {
                int pos = atomicAdd(&g_amb_cnt, 1);
                g_amb_row[pos] = row0 + row;
                float lim = s4[1] + TH;
                int nc = 0;
                for (int w = 0; w < 4; w++)
                    for (int q = 0; q < 4; q++) {
                        float v = candv[(row * 4 + w) * 4 + q];
                        if (v <= lim && nc < MAXC)
                            g_amb_cand[pos][nc++] = candi[(row * 4 + w) * 4 + q];
                    }
                g_amb_n[pos] = nc;
            }
        }
        __syncthreads();

        // ---- gather: out[row] = centroids[sidx[row]] ----
        #pragma unroll 4
        for (int idx = tid; idx < BM * (DIM / 4); idx += THREADS) {
            int r = idx >> 7, c = idx & 127;
            float4 v = *(const float4*)(cent + (size_t)sidx[r] * DIM + c * 4);
            *(float4*)(out + (size_t)(row0 + r) * DIM + c * 4) = v;
        }
        __syncthreads();   // sidx/cand reads done before next tile's claim
    }
}

// ---------------------------------------------------------------------------
// rescue: exact fp32 rescoring of ambiguous rows (one warp per row)
// ---------------------------------------------------------------------------
__global__ void rescue_kernel(const float* __restrict__ emb,
                              const float* __restrict__ cent,
                              float* __restrict__ out) {
    int gw   = (blockIdx.x * blockDim.x + threadIdx.x) >> 5;
    int lane = threadIdx.x & 31;
    int nw   = (gridDim.x * blockDim.x) >> 5;
    int cnt  = g_amb_cnt;

    for (int e = gw; e < cnt; e += nw) {
        int row = g_amb_row[e];
        int nc  = g_amb_n[e];
        const float* er = emb + (size_t)row * DIM;
        float fv[16];
        #pragma unroll
        for (int i = 0; i < 4; i++) {
            float4 v = *(const float4*)(er + (lane + i * 32) * 4);
            fv[i * 4 + 0] = v.x; fv[i * 4 + 1] = v.y;
            fv[i * 4 + 2] = v.z; fv[i * 4 + 3] = v.w;
        }
        float b1 = FLT_MAX, b2 = FLT_MAX;
        int   j1 = 0x7fffffff, j2 = 0x7fffffff;
        for (int q = 0; q < nc; q++) {
            int c = g_amb_cand[e][q];
            const float* cr = cent + (size_t)c * DIM;
            float p = 0.f;
            #pragma unroll
            for (int i = 0; i < 4; i++) {
                float4 u = *(const float4*)(cr + (lane + i * 32) * 4);
                p = fmaf(fv[i * 4 + 0], u.x, p);
                p = fmaf(fv[i * 4 + 1], u.y, p);
                p = fmaf(fv[i * 4 + 2], u.z, p);
                p = fmaf(fv[i * 4 + 3], u.w, p);
            }
            #pragma unroll
            for (int o = 16; o; o >>= 1) p += __shfl_xor_sync(0xFFFFFFFFu, p, o);
            float sc = fmaf(-2.0f, p, g_cn2[c]);
            if (closer(sc, c, b1, j1)) {
                b2 = b1; j2 = j1; b1 = sc; j1 = c;
            } else if (closer(sc, c, b2, j2)) {
                b2 = sc; j2 = c;
            }
        }
        const float* cr = cent + (size_t)j2 * DIM;
        float* orow = out + (size_t)row * DIM;
        #pragma unroll
        for (int i = 0; i < 4; i++) {
            *(float4*)(orow + (lane + i * 32) * 4) =
                *(const float4*)(cr + (lane + i * 32) * 4);
        }
    }
}

extern "C" void kernel_launch(void* const* d_in, const int* in_sizes, int n_in,
                              void* d_out, int out_size) {
    const float* emb  = (const float*)d_in[0];
    const float* cent = (const float*)d_in[1];
    float*       out  = (float*)d_out;

    cudaFuncSetAttribute(negsample_mma_kernel,
                         cudaFuncAttributeMaxDynamicSharedMemorySize, SMEM_BYTES);

    prep_kernel<<<KCENT, 256>>>(cent);
    negsample_mma_kernel<<<NCTAS, THREADS, SMEM_BYTES>>>(emb, cent, out);
    rescue_kernel<<<512, 256>>>(emb, cent, out);
}

// round 12
// speedup vs baseline: 1.2861x; 1.2861x over previous
#include <cuda_runtime.h>
#include <cuda_fp16.h>
#include <cstdint>
#include <float.h>

#define NROWS   65536
#define DIM     512
#define KCENT   256
#define BM      32           // rows per tile (halved: occupancy play)
#define KC      64           // fp16 k-chunk (128B per row -> SW128)
#define NCHUNK  (DIM / KC)   // 8
#define NTILES  (NROWS / BM) // 2048
#define THREADS 256
#define NCTAS   444          // 3 per SM, persistent
#define TH      0.8f         // certainty margin (validated R6)
#define MAXC    16

// ---------------------------------------------------------------------------
// device globals (scratch; no allocs allowed)
// ---------------------------------------------------------------------------
__device__ float   g_cn2[KCENT];
__device__ __half  g_chf[KCENT * DIM];
__device__ int     g_tile_ctr;
__device__ int     g_amb_cnt;
__device__ int     g_amb_row[NROWS];
__device__ int     g_amb_n[NROWS];
__device__ int     g_amb_cand[NROWS][MAXC];

// ---------------------------------------------------------------------------
// helpers
// ---------------------------------------------------------------------------
__device__ __forceinline__ uint32_t smem_u32(const void* p) {
    uint32_t a;
    asm("{ .reg .u64 t; cvta.to.shared.u64 t, %1; cvt.u32.u64 %0, t; }"
        : "=r"(a) : "l"(p));
    return a;
}
__device__ __forceinline__ uint32_t swz(uint32_t o) { return o ^ ((o >> 3) & 0x70); }

#define LDM_X4(r, addr)                                                     \
    asm volatile("ldmatrix.sync.aligned.m8n8.x4.shared.b16 {%0,%1,%2,%3}, [%4];" \
        : "=r"((r)[0]), "=r"((r)[1]), "=r"((r)[2]), "=r"((r)[3]) : "r"(addr))
#define LDM_X2(r0, r1, addr)                                                \
    asm volatile("ldmatrix.sync.aligned.m8n8.x2.shared.b16 {%0,%1}, [%2];"  \
        : "=r"(r0), "=r"(r1) : "r"(addr))
// fp16 inputs, fp16 ACCUMULATE (packed f16x2 D/C regs)
#define MMA_F16ACC(d, a, b0, b1)                                            \
    asm volatile("mma.sync.aligned.m16n8k16.row.col.f16.f16.f16.f16 "       \
        "{%0,%1}, {%2,%3,%4,%5}, {%6,%7}, {%0,%1};"                         \
        : "+r"((d)[0]), "+r"((d)[1])                                        \
        : "r"((a)[0]), "r"((a)[1]), "r"((a)[2]), "r"((a)[3]), "r"(b0), "r"(b1))
#define CP_ASYNC16(dst, src)                                                \
    asm volatile("cp.async.cg.shared.global [%0], [%1], 16;" :: "r"(dst), "l"(src))
#define CP_COMMIT() asm volatile("cp.async.commit_group;" ::: "memory")
#define CP_WAIT0()  asm volatile("cp.async.wait_group 0;" ::: "memory")

__device__ __forceinline__ bool closer(float s, int i, float s2, int i2) {
    return (s < s2) || (s == s2 && i < i2);
}
__device__ __forceinline__ void ins4(float v, int i, float s[4], int ix[4]) {
    if (closer(v, i, s[3], ix[3])) {
        s[3] = v; ix[3] = i;
        #pragma unroll
        for (int q = 3; q > 0; q--) {
            if (closer(s[q], ix[q], s[q - 1], ix[q - 1])) {
                float tv = s[q];  s[q] = s[q - 1];  s[q - 1] = tv;
                int   ti = ix[q]; ix[q] = ix[q - 1]; ix[q - 1] = ti;
            }
        }
    }
}

// ---------------------------------------------------------------------------
// prep: exact centroid norms + fp16 centroid copy + zero counters
// ---------------------------------------------------------------------------
__global__ void prep_kernel(const float* __restrict__ cent) {
    __shared__ float ws[8];
    int b = blockIdx.x, t = threadIdx.x;
    if (b == 0 && t == 0) { g_amb_cnt = 0; g_tile_ctr = 0; }
    float v0 = cent[b * DIM + 2 * t];
    float v1 = cent[b * DIM + 2 * t + 1];
    g_chf[b * DIM + 2 * t]     = __float2half_rn(v0);
    g_chf[b * DIM + 2 * t + 1] = __float2half_rn(v1);
    float p = fmaf(v0, v0, v1 * v1);
    #pragma unroll
    for (int o = 16; o; o >>= 1) p += __shfl_xor_sync(0xFFFFFFFFu, p, o);
    if ((t & 31) == 0) ws[t >> 5] = p;
    __syncthreads();
    if (t == 0) {
        float s = 0.f;
        #pragma unroll
        for (int w = 0; w < 8; w++) s += ws[w];
        g_cn2[b] = s;
    }
}

// ---------------------------------------------------------------------------
// main: persistent CTAs (dynamic tile claim). 32-row tile x 256 centroids,
// warp tile 16x64 (acc=32 regs -> 3 CTAs/SM, 24 warps). fp16 mma.sync
// (f16 acc per chunk -> fp32), SW128 smem, double-buffered, top-4, gather.
// dyn smem: A 4K x2 | B 32K x2 = 72K.
// ---------------------------------------------------------------------------
#define OFF_A0    0
#define OFF_A1    4096
#define OFF_B0    8192
#define OFF_B1    40960
#define SMEM_BYTES 73728

__global__ __launch_bounds__(THREADS, 3)
void negsample_mma_kernel(const float* __restrict__ emb,
                          const float* __restrict__ cent,
                          float* __restrict__ out) {
    extern __shared__ __align__(128) char smem[];
    __shared__ float cns[KCENT];
    __shared__ int   sidx[BM];
    __shared__ int   snext;

    const uint32_t sb = smem_u32(smem);
    const int tid  = threadIdx.x;
    const int lane = tid & 31;
    const int wid  = tid >> 5;
    const int wr   = wid >> 2;        // 0..1 (16-row half)
    const int wc   = wid & 3;         // 0..3 (col quarter)

    cns[tid] = g_cn2[tid];

    const uint32_t offA[2] = {OFF_A0, OFF_A1};
    const uint32_t offB[2] = {OFF_B0, OFF_B1};

    const int ar  = tid >> 4;         // A gmem row base (0..15; +16 per i)
    const int ac4 = tid & 15;
    const int br  = tid >> 3;         // B gmem row base (0..31; +32 per i)
    const int bg  = tid & 7;

    float* candv = (float*)(smem);          // [32][4][4] -> 2KB (aliases A0)
    int*   candi = (int*)(smem + 2048);     // [32][4][4] -> 2KB

    while (true) {
        if (tid == 0) snext = atomicAdd(&g_tile_ctr, 1);
        __syncthreads();
        const int tile = snext;
        if (tile >= NTILES) break;
        const int row0 = tile * BM;

        float acc[8][4];
        #pragma unroll
        for (int j = 0; j < 8; j++)
            #pragma unroll
            for (int q = 0; q < 4; q++) acc[j][q] = 0.f;

        // ---- prologue: A regs chunk 0, cp.async B chunk 0 -> buf 0 ----
        float4 areg[2];
        {
            const float* ebase = emb + (size_t)row0 * DIM;
            #pragma unroll
            for (int i = 0; i < 2; i++)
                areg[i] = *(const float4*)(ebase + (size_t)(ar + i * 16) * DIM + ac4 * 4);
            #pragma unroll
            for (int i = 0; i < 8; i++) {
                int r = br + i * 32;
                CP_ASYNC16(sb + OFF_B0 + swz((uint32_t)(r * 128 + bg * 16)),
                           g_chf + (size_t)r * DIM + bg * 8);
            }
            CP_COMMIT();
        }

        for (int kc = 0; kc < NCHUNK; kc++) {
            const int cur = kc & 1;

            // ---- convert prefetched A regs -> fp16 smem (swizzled) ----
            #pragma unroll
            for (int i = 0; i < 2; i++) {
                __half2 h0 = __floats2half2_rn(areg[i].x, areg[i].y);
                __half2 h1 = __floats2half2_rn(areg[i].z, areg[i].w);
                uint32_t bo = swz((uint32_t)((ar + i * 16) * 128 + ac4 * 8));
                *(uint2*)(smem + offA[cur] + bo) =
                    make_uint2(*(uint32_t*)&h0, *(uint32_t*)&h1);
            }
            CP_WAIT0();
            __syncthreads();

            // ---- prefetch next chunk (overlaps MMA) ----
            if (kc + 1 < NCHUNK) {
                const float* ebase = emb + (size_t)row0 * DIM + (kc + 1) * KC;
                #pragma unroll
                for (int i = 0; i < 2; i++)
                    areg[i] = *(const float4*)(ebase + (size_t)(ar + i * 16) * DIM + ac4 * 4);
                #pragma unroll
                for (int i = 0; i < 8; i++) {
                    int r = br + i * 32;
                    CP_ASYNC16(sb + offB[1 - cur] + swz((uint32_t)(r * 128 + bg * 16)),
                               g_chf + (size_t)r * DIM + (kc + 1) * KC + bg * 8);
                }
                CP_COMMIT();
            }

            // ---- f16 acc within chunk, promote to fp32 ----
            uint32_t cf[8][2];
            #pragma unroll
            for (int j = 0; j < 8; j++) { cf[j][0] = 0u; cf[j][1] = 0u; }

            #pragma unroll
            for (int s = 0; s < 4; s++) {
                const int kb = s * 32;
                uint32_t a[4];
                int m = wr * 16 + (lane & 15);
                LDM_X4(a, sb + offA[cur] +
                       swz((uint32_t)(m * 128 + kb + ((lane >> 4) << 4))));
                #pragma unroll
                for (int j = 0; j < 8; j++) {
                    int n = wc * 64 + j * 8 + (lane & 7);
                    uint32_t b0, b1;
                    LDM_X2(b0, b1, sb + offB[cur] +
                           swz((uint32_t)(n * 128 + kb + (((lane >> 3) & 1) << 4))));
                    MMA_F16ACC(cf[j], a, b0, b1);
                }
            }
            #pragma unroll
            for (int j = 0; j < 8; j++) {
                float2 f0 = __half22float2(*(__half2*)&cf[j][0]);
                float2 f1 = __half22float2(*(__half2*)&cf[j][1]);
                acc[j][0] += f0.x; acc[j][1] += f0.y;
                acc[j][2] += f1.x; acc[j][3] += f1.y;
            }
            // no trailing sync: next iter writes the opposite buffer only
        }
        __syncthreads();   // all MMA smem reads done -> reuse smem for candidates

        // ---- per-lane scores + top-4 per row; merge across 4 lanes ----
        #pragma unroll
        for (int h = 0; h < 2; h++) {
            int row = wr * 16 + h * 8 + (lane >> 2);
            float s4[4]; int i4[4];
            #pragma unroll
            for (int q = 0; q < 4; q++) { s4[q] = FLT_MAX; i4[q] = 0x7fffffff; }
            #pragma unroll
            for (int j = 0; j < 8; j++) {
                #pragma unroll
                for (int b = 0; b < 2; b++) {
                    int   col = wc * 64 + j * 8 + (lane & 3) * 2 + b;
                    float sc  = fmaf(-2.0f, acc[j][h * 2 + b], cns[col]);
                    ins4(sc, col, s4, i4);
                }
            }
            // butterfly merge: snapshot partner entries BEFORE inserting
            #pragma unroll
            for (int off = 1; off <= 2; off <<= 1) {
                float ov[4]; int oi[4];
                #pragma unroll
                for (int q = 0; q < 4; q++) {
                    ov[q] = __shfl_xor_sync(0xFFFFFFFFu, s4[q], off);
                    oi[q] = __shfl_xor_sync(0xFFFFFFFFu, i4[q], off);
                }
                #pragma unroll
                for (int q = 0; q < 4; q++) ins4(ov[q], oi[q], s4, i4);
            }
            if ((lane & 3) == 0) {
                int base = (row * 4 + wc) * 4;
                #pragma unroll
                for (int q = 0; q < 4; q++) { candv[base + q] = s4[q]; candi[base + q] = i4[q]; }
            }
        }
        __syncthreads();

        // ---- final per-row merge of 16 candidates; certainty test ----
        if (tid < BM) {
            int row = tid;
            float s4[4]; int i4[4];
            #pragma unroll
            for (int q = 0; q < 4; q++) { s4[q] = FLT_MAX; i4[q] = 0x7fffffff; }
            #pragma unroll
            for (int w = 0; w < 4; w++)
                #pragma unroll
                for (int q = 0; q < 4; q++)
                    ins4(candv[(row * 4 + w) * 4 + q], candi[(row * 4 + w) * 4 + q], s4, i4);

            sidx[row] = i4[1];
            bool amb = (s4[1] - s4[0] <= TH) || (s4[2] - s4[1] <= TH);
            if (amb) {
                int pos = atomicAdd(&g_amb_cnt, 1);
                g_amb_row[pos] = row0 + row;
                float lim = s4[1] + TH;
                int nc = 0;
                for (int w = 0; w < 4; w++)
                    for (int q = 0; q < 4; q++) {
                        float v = candv[(row * 4 + w) * 4 + q];
                        if (v <= lim && nc < MAXC)
                            g_amb_cand[pos][nc++] = candi[(row * 4 + w) * 4 + q];
                    }
                g_amb_n[pos] = nc;
            }
        }
        __syncthreads();

        // ---- gather: out[row] = centroids[sidx[row]] ----
        #pragma unroll 4
        for (int idx = tid; idx < BM * (DIM / 4); idx += THREADS) {
            int r = idx >> 7, c = idx & 127;
            float4 v = *(const float4*)(cent + (size_t)sidx[r] * DIM + c * 4);
            *(float4*)(out + (size_t)(row0 + r) * DIM + c * 4) = v;
        }
        __syncthreads();   // sidx/cand reads done before next tile's claim
    }
}

// ---------------------------------------------------------------------------
// rescue: exact fp32 rescoring of ambiguous rows (one warp per row)
// ---------------------------------------------------------------------------
__global__ void rescue_kernel(const float* __restrict__ emb,
                              const float* __restrict__ cent,
                              float* __restrict__ out) {
    int gw   = (blockIdx.x * blockDim.x + threadIdx.x) >> 5;
    int lane = threadIdx.x & 31;
    int nw   = (gridDim.x * blockDim.x) >> 5;
    int cnt  = g_amb_cnt;

    for (int e = gw; e < cnt; e += nw) {
        int row = g_amb_row[e];
        int nc  = g_amb_n[e];
        const float* er = emb + (size_t)row * DIM;
        float fv[16];
        #pragma unroll
        for (int i = 0; i < 4; i++) {
            float4 v = *(const float4*)(er + (lane + i * 32) * 4);
            fv[i * 4 + 0] = v.x; fv[i * 4 + 1] = v.y;
            fv[i * 4 + 2] = v.z; fv[i * 4 + 3] = v.w;
        }
        float b1 = FLT_MAX, b2 = FLT_MAX;
        int   j1 = 0x7fffffff, j2 = 0x7fffffff;
        for (int q = 0; q < nc; q++) {
            int c = g_amb_cand[e][q];
            const float* cr = cent + (size_t)c * DIM;
            float p = 0.f;
            #pragma unroll
            for (int i = 0; i < 4; i++) {
                float4 u = *(const float4*)(cr + (lane + i * 32) * 4);
                p = fmaf(fv[i * 4 + 0], u.x, p);
                p = fmaf(fv[i * 4 + 1], u.y, p);
                p = fmaf(fv[i * 4 + 2], u.z, p);
                p = fmaf(fv[i * 4 + 3], u.w, p);
            }
            #pragma unroll
            for (int o = 16; o; o >>= 1) p += __shfl_xor_sync(0xFFFFFFFFu, p, o);
            float sc = fmaf(-2.0f, p, g_cn2[c]);
            if (closer(sc, c, b1, j1)) {
                b2 = b1; j2 = j1; b1 = sc; j1 = c;
            } else if (closer(sc, c, b2, j2)) {
                b2 = sc; j2 = c;
            }
        }
        const float* cr = cent + (size_t)j2 * DIM;
        float* orow = out + (size_t)row * DIM;
        #pragma unroll
        for (int i = 0; i < 4; i++) {
            *(float4*)(orow + (lane + i * 32) * 4) =
                *(const float4*)(cr + (lane + i * 32) * 4);
        }
    }
}

extern "C" void kernel_launch(void* const* d_in, const int* in_sizes, int n_in,
                              void* d_out, int out_size) {
    const float* emb  = (const float*)d_in[0];
    const float* cent = (const float*)d_in[1];
    float*       out  = (float*)d_out;

    cudaFuncSetAttribute(negsample_mma_kernel,
                         cudaFuncAttributeMaxDynamicSharedMemorySize, SMEM_BYTES);

    prep_kernel<<<KCENT, 256>>>(cent);
    negsample_mma_kernel<<<NCTAS, THREADS, SMEM_BYTES>>>(emb, cent, out);
    rescue_kernel<<<512, 256>>>(emb, cent, out);
}